// round 5
// baseline (speedup 1.0000x reference)
#include <cuda_runtime.h>
#include <math.h>

#define Bn 4
#define Cn 64
#define Hn 128
#define Wn 128
#define Pn 63
#define HW (Hn*Wn)
#define NG 16   /* channel groups of 4 */

typedef unsigned long long u64t;

// Packed (batch-paired) scratch: lane0 = batch bp, lane1 = batch bp+2
__device__ u64t g_g0p[2*Cn*HW];     // grad-act(c0), packed float2
__device__ u64t g_a1p[2*HW];        // act(c1), packed
__device__ u64t g_partp[NG*2*HW];   // partial sums, packed

__constant__ float c_f0[Cn*25];
__constant__ float c_f1[Cn*25];
__constant__ float c_b0[Cn];
__constant__ float c_b1[1];

__device__ __forceinline__ float ex2f_(float x){ float r; asm("ex2.approx.f32 %0,%1;" : "=f"(r) : "f"(x)); return r; }
__device__ __forceinline__ float rcpf_(float x){ float r; asm("rcp.approx.f32 %0,%1;" : "=f"(r) : "f"(x)); return r; }

__device__ __forceinline__ u64t pack2(float lo, float hi){ u64t r; asm("mov.b64 %0,{%1,%2};" : "=l"(r) : "f"(lo), "f"(hi)); return r; }
__device__ __forceinline__ void unpack2(u64t v, float& lo, float& hi){ asm("mov.b64 {%0,%1},%2;" : "=f"(lo), "=f"(hi) : "l"(v)); }
__device__ __forceinline__ u64t fma2(u64t a, u64t b, u64t c){ u64t d; asm("fma.rn.f32x2 %0,%1,%2,%3;" : "=l"(d) : "l"(a), "l"(b), "l"(c)); return d; }
__device__ __forceinline__ u64t mul2(u64t a, u64t b){ u64t d; asm("mul.rn.f32x2 %0,%1,%2;" : "=l"(d) : "l"(a), "l"(b)); return d; }
__device__ __forceinline__ u64t add2(u64t a, u64t b){ u64t d; asm("add.rn.f32x2 %0,%1,%2;" : "=l"(d) : "l"(a), "l"(b)); return d; }

#define CJ1 0.60653065971f
#define CJ2 0.13533528324f
#define CJ3 0.01110899654f
#define CJ4 0.00033546262f
#define L2E 1.44269504089f

// 9-tap RBF via exp decomposition (scalar)
__device__ __forceinline__ void rbf9(float v, const float* __restrict__ w,
                                     float& a_out, float& g_out) {
    float u  = fmaf(v, 0.1f, 31.0f);
    float pf = rintf(u);
    pf = fminf(fmaxf(pf, 4.0f), 58.0f);
    int   pc = (int)pf;
    float s  = u - pf;
    s = fminf(fmaxf(s, -9.0f), 9.0f);
    float r  = ex2f_(s * L2E);
    float E0 = ex2f_(s * s * (-0.5f * L2E));
    float q  = rcpf_(r);
    float r2 = r*r, r3 = r2*r, r4 = r2*r2;
    float q2 = q*q, q3 = q2*q, q4 = q2*q2;
    float m, A, B;
    m = w[pc-4]*(CJ4*q4); A  = m;  B = m * -4.0f;
    m = w[pc-3]*(CJ3*q3); A += m;  B = fmaf(m, -3.0f, B);
    m = w[pc-2]*(CJ2*q2); A += m;  B = fmaf(m, -2.0f, B);
    m = w[pc-1]*(CJ1*q ); A += m;  B = fmaf(m, -1.0f, B);
    m = w[pc  ];          A += m;
    m = w[pc+1]*(CJ1*r ); A += m;  B = fmaf(m,  1.0f, B);
    m = w[pc+2]*(CJ2*r2); A += m;  B = fmaf(m,  2.0f, B);
    m = w[pc+3]*(CJ3*r3); A += m;  B = fmaf(m,  3.0f, B);
    m = w[pc+4]*(CJ4*r4); A += m;  B = fmaf(m,  4.0f, B);
    a_out = E0 * A;
    g_out = (-0.1f * E0) * fmaf(s, A, -B);
}

__device__ __forceinline__ void ld8(const u64t* p, u64t v[8]) {
    ulonglong2 A = *(const ulonglong2*)(p + 0);
    ulonglong2 B = *(const ulonglong2*)(p + 2);
    ulonglong2 C = *(const ulonglong2*)(p + 4);
    ulonglong2 D = *(const ulonglong2*)(p + 6);
    v[0]=A.x; v[1]=A.y; v[2]=B.x; v[3]=B.y;
    v[4]=C.x; v[5]=C.y; v[6]=D.x; v[7]=D.y;
}

// kA: fused conv0 + RBF + conv1-partials. Tile = 8 rows x 128 cols, batch-pair,
// 4 channels. grid (16, 2, 16).
__global__ void __launch_bounds__(256) kA_enc(const float* __restrict__ x,
                                              const float* __restrict__ w0) {
    __shared__ __align__(16) u64t xsp[16][132];  // rows h0-4..h0+11 clamp, cols -2..129 clamp
    __shared__ __align__(16) u64t sa0p[12][136]; // a0 rows h0-2..h0+9 clamp, cols -2..129 rep
    __shared__ float sw0[4*63];
    int tid = threadIdx.x;
    int h0 = blockIdx.x * 8;
    int bp = blockIdx.y;            // batches (bp, bp+2)
    int g  = blockIdx.z;

    for (int i = tid; i < 4*63; i += 256) sw0[i] = w0[(g*4)*63 + i];
    const float* x0 = x + bp*HW;
    const float* x1 = x + (bp+2)*HW;
    for (int i = tid; i < 16*132; i += 256) {
        int r = i / 132, c = i - r*132;
        int gh = min(max(h0 - 4 + r, 0), Hn-1);
        int gw = min(max(c - 2, 0), Wn-1);
        int idx = gh*Wn + gw;
        (&xsp[0][0])[i] = pack2(x0[idx]*255.0f, x1[idx]*255.0f);
    }

    u64t acc[4] = {0,0,0,0};
    int tr = tid >> 5;            // 0..7 out row
    int tw = (tid & 31) * 4;      // out col base

    #pragma unroll 1
    for (int cc = 0; cc < 4; ++cc) {
        int c = g*4 + cc;
        u64t bias2 = pack2(c_b0[c], c_b0[c]);
        __syncthreads();
        // a0 stage: 12 rows x 32 strips = 384 units
        #pragma unroll 1
        for (int u = tid; u < 384; u += 256) {
            int ri = u >> 5;
            int s  = u & 31;
            int w  = s * 4;
            int hc = min(max(h0 - 2 + ri, 0), Hn-1);
            int xr = hc - h0 + 2;       // xs row idx for dy=0
            u64t a0=bias2, a1=bias2, a2=bias2, a3=bias2;
            #pragma unroll
            for (int dy = 0; dy < 5; ++dy) {
                u64t v[8]; ld8(&xsp[xr+dy][w], v);
                #pragma unroll
                for (int dx = 0; dx < 5; ++dx) {
                    float f = c_f0[c*25 + dy*5 + dx];
                    u64t ff = pack2(f, f);
                    a0 = fma2(v[dx+0], ff, a0);
                    a1 = fma2(v[dx+1], ff, a1);
                    a2 = fma2(v[dx+2], ff, a2);
                    a3 = fma2(v[dx+3], ff, a3);
                }
            }
            const float* wr = &sw0[cc*63];
            float lo, hi, aL, aH, gL, gH;
            u64t av[4], gv[4];
            unpack2(a0, lo, hi); rbf9(lo, wr, aL, gL); rbf9(hi, wr, aH, gH);
            av[0]=pack2(aL,aH); gv[0]=pack2(gL,gH);
            unpack2(a1, lo, hi); rbf9(lo, wr, aL, gL); rbf9(hi, wr, aH, gH);
            av[1]=pack2(aL,aH); gv[1]=pack2(gL,gH);
            unpack2(a2, lo, hi); rbf9(lo, wr, aL, gL); rbf9(hi, wr, aH, gH);
            av[2]=pack2(aL,aH); gv[2]=pack2(gL,gH);
            unpack2(a3, lo, hi); rbf9(lo, wr, aL, gL); rbf9(hi, wr, aH, gH);
            av[3]=pack2(aL,aH); gv[3]=pack2(gL,gH);
            *(ulonglong2*)&sa0p[ri][2+w]   = make_ulonglong2(av[0], av[1]);
            *(ulonglong2*)&sa0p[ri][2+w+2] = make_ulonglong2(av[2], av[3]);
            if (s == 0)  { sa0p[ri][0]   = av[0]; sa0p[ri][1]   = av[0]; }
            if (s == 31) { sa0p[ri][130] = av[3]; sa0p[ri][131] = av[3]; }
            if (ri >= 2 && ri <= 9) {
                u64t* gp = &g_g0p[(size_t)(bp*Cn + c)*HW + (h0 + ri - 2)*Wn + w];
                *(ulonglong2*)(gp)     = make_ulonglong2(gv[0], gv[1]);
                *(ulonglong2*)(gp + 2) = make_ulonglong2(gv[2], gv[3]);
            }
        }
        __syncthreads();
        // conv1 accumulate: 1 strip per thread (8 rows x 32 strips)
        #pragma unroll
        for (int ky = 0; ky < 5; ++ky) {
            u64t v[8]; ld8(&sa0p[tr+ky][tw], v);
            #pragma unroll
            for (int kx = 0; kx < 5; ++kx) {
                float f = c_f1[c*25 + ky*5 + kx];
                u64t ff = pack2(f, f);
                acc[0] = fma2(v[kx+0], ff, acc[0]);
                acc[1] = fma2(v[kx+1], ff, acc[1]);
                acc[2] = fma2(v[kx+2], ff, acc[2]);
                acc[3] = fma2(v[kx+3], ff, acc[3]);
            }
        }
    }
    u64t* pp = &g_partp[(size_t)g*(2*HW) + bp*HW + (h0+tr)*Wn + tw];
    *(ulonglong2*)(pp)     = make_ulonglong2(acc[0], acc[1]);
    *(ulonglong2*)(pp + 2) = make_ulonglong2(acc[2], acc[3]);
}

// K2b: a1 = act(sum(partials) + b1, w1), packed
__global__ void k2b_reduce_act(const float* __restrict__ w1) {
    __shared__ float sw[Pn];
    int tid = threadIdx.x;
    if (tid < Pn) sw[tid] = w1[tid];
    __syncthreads();
    int pp = blockIdx.x * 256 + tid;     // packed pixel in [0, 2*HW)
    u64t s2 = pack2(c_b1[0], c_b1[0]);
    #pragma unroll
    for (int g = 0; g < NG; ++g) s2 = add2(s2, g_partp[g*(2*HW) + pp]);
    float lo, hi, aL, aH, gL, gH;
    unpack2(s2, lo, hi);
    rbf9(lo, sw, aL, gL);
    rbf9(hi, sw, aH, gH);
    g_a1p[pp] = pack2(aL, aH);
}

// K5: fused deconv1*g0 + deconv0-partials. Tile = 8 rows x 128 cols, batch-pair,
// 4 channels. grid (16, 2, 16).
__global__ void __launch_bounds__(256) k5_fused_deconv() {
    __shared__ __align__(16) u64t sa1p[16][136];  // a1 rows h0-4..h0+11, cols -4..131, zero pad
    __shared__ __align__(16) u64t sdp[12][132];   // d rows h0-2..h0+9, cols -2..129 (0 outside)
    int tid = threadIdx.x;
    int h0 = blockIdx.x * 8;
    int bp = blockIdx.y;
    int g  = blockIdx.z;
    const u64t* ab = g_a1p + bp*HW;

    for (int i = tid; i < 16*136; i += 256) {
        int r = i / 136, c = i - r*136;
        int gh = h0 - 4 + r, gw = c - 4;
        (&sa1p[0][0])[i] = ((unsigned)gh < (unsigned)Hn && (unsigned)gw < (unsigned)Wn)
                           ? ab[gh*Wn + gw] : 0ULL;
    }

    u64t acc[4] = {0,0,0,0};
    int tr = tid >> 5;
    int tw = (tid & 31) * 4;

    #pragma unroll 1
    for (int cc = 0; cc < 4; ++cc) {
        int c = g*4 + cc;
        const u64t* g0c = g_g0p + (size_t)(bp*Cn + c)*HW;
        __syncthreads();
        // d stage: 12 rows x 33 strips = 396 units
        #pragma unroll 1
        for (int u = tid; u < 396; u += 256) {
            int r  = u / 33;
            int s  = u - r*33;
            int c0 = s * 4;               // sd col idx base; d col = c0+j-2
            int hd = h0 - 2 + r;
            u64t d0=0, d1=0, d2=0, d3=0;
            #pragma unroll
            for (int ky = 0; ky < 5; ++ky) {
                u64t v[8]; ld8(&sa1p[r+ky][c0], v);
                #pragma unroll
                for (int kx = 0; kx < 5; ++kx) {
                    float f = c_f1[c*25 + 24 - (ky*5 + kx)];
                    u64t ff = pack2(f, f);
                    d0 = fma2(v[kx+0], ff, d0);
                    d1 = fma2(v[kx+1], ff, d1);
                    d2 = fma2(v[kx+2], ff, d2);
                    d3 = fma2(v[kx+3], ff, d3);
                }
            }
            bool rv = (unsigned)hd < (unsigned)Hn;
            int hs = min(max(hd, 0), Hn-1);
            const u64t* g0r = g0c + hs*Wn;
            int w0c = c0 - 2;
            int wa = min(max(w0c+0, 0), Wn-1);
            int wb = min(max(w0c+1, 0), Wn-1);
            int wc = min(max(w0c+2, 0), Wn-1);
            int wd = min(max(w0c+3, 0), Wn-1);
            d0 = (rv && (unsigned)(w0c+0) < (unsigned)Wn) ? mul2(d0, g0r[wa]) : 0ULL;
            d1 = (rv && (unsigned)(w0c+1) < (unsigned)Wn) ? mul2(d1, g0r[wb]) : 0ULL;
            d2 = (rv && (unsigned)(w0c+2) < (unsigned)Wn) ? mul2(d2, g0r[wc]) : 0ULL;
            d3 = (rv && (unsigned)(w0c+3) < (unsigned)Wn) ? mul2(d3, g0r[wd]) : 0ULL;
            *(ulonglong2*)&sdp[r][c0]   = make_ulonglong2(d0, d1);
            *(ulonglong2*)&sdp[r][c0+2] = make_ulonglong2(d2, d3);
        }
        __syncthreads();
        // deconv0 accumulate: 1 strip per thread
        #pragma unroll
        for (int ky = 0; ky < 5; ++ky) {
            u64t v[8]; ld8(&sdp[tr+ky][tw], v);
            #pragma unroll
            for (int kx = 0; kx < 5; ++kx) {
                float f = c_f0[c*25 + 24 - (ky*5 + kx)];
                u64t ff = pack2(f, f);
                acc[0] = fma2(v[kx+0], ff, acc[0]);
                acc[1] = fma2(v[kx+1], ff, acc[1]);
                acc[2] = fma2(v[kx+2], ff, acc[2]);
                acc[3] = fma2(v[kx+3], ff, acc[3]);
            }
        }
    }
    u64t* pp = &g_partp[(size_t)g*(2*HW) + bp*HW + (h0+tr)*Wn + tw];
    *(ulonglong2*)(pp)     = make_ulonglong2(acc[0], acc[1]);
    *(ulonglong2*)(pp + 2) = make_ulonglong2(acc[2], acc[3]);
}

// K4b: out = x - sum(partials)/255 - exp(lam)*(x - y), unpack lanes
__global__ void k4b_reduce_out(const float* __restrict__ x,
                               const float* __restrict__ y,
                               const float* __restrict__ lam_param,
                               float* __restrict__ out) {
    int pp = blockIdx.x * 256 + threadIdx.x;
    int bp = pp >> 14;           // / HW
    int p  = pp & (HW - 1);
    u64t s2 = 0;
    #pragma unroll
    for (int g = 0; g < NG; ++g) s2 = add2(s2, g_partp[g*(2*HW) + pp]);
    float sL, sH;
    unpack2(s2, sL, sH);
    float e = __expf(lam_param[0]);
    int iL = bp*HW + p, iH = (bp+2)*HW + p;
    float xL = x[iL], yL = y[iL];
    float xH = x[iH], yH = y[iH];
    out[iL] = xL - sL*(1.0f/255.0f) - e*(xL - yL);
    out[iH] = xH - sH*(1.0f/255.0f) - e*(xH - yH);
}

extern "C" void kernel_launch(void* const* d_in, const int* in_sizes, int n_in,
                              void* d_out, int out_size) {
    const float* x   = (const float*)d_in[0];
    const float* y   = (const float*)d_in[1];
    // d_in[2] = lam (ignored)
    const float* f0  = (const float*)d_in[3];
    const float* b0  = (const float*)d_in[4];
    const float* f1  = (const float*)d_in[5];
    const float* b1  = (const float*)d_in[6];
    const float* w0  = (const float*)d_in[7];
    const float* w1  = (const float*)d_in[8];
    const float* lam = (const float*)d_in[9];
    float* out = (float*)d_out;

    cudaMemcpyToSymbolAsync(c_f0, f0, Cn*25*sizeof(float), 0, cudaMemcpyDeviceToDevice, 0);
    cudaMemcpyToSymbolAsync(c_f1, f1, Cn*25*sizeof(float), 0, cudaMemcpyDeviceToDevice, 0);
    cudaMemcpyToSymbolAsync(c_b0, b0, Cn*sizeof(float),    0, cudaMemcpyDeviceToDevice, 0);
    cudaMemcpyToSymbolAsync(c_b1, b1, sizeof(float),       0, cudaMemcpyDeviceToDevice, 0);

    dim3 gT(Hn/8, Bn/2, NG);       // (16, 2, 16) = 512 CTAs
    dim3 gR(2*HW/256);             // (128)

    kA_enc<<<gT, 256>>>(x, w0);
    k2b_reduce_act<<<gR, 256>>>(w1);
    k5_fused_deconv<<<gT, 256>>>();
    k4b_reduce_out<<<gR, 256>>>(x, y, lam, out);
}

// round 6
// speedup vs baseline: 1.3147x; 1.3147x over previous
#include <cuda_runtime.h>
#include <math.h>

#define Bn 4
#define Cn 64
#define Hn 128
#define Wn 128
#define Pn 63
#define HW (Hn*Wn)
#define NG 32   /* channel groups of 2 */

// Scratch (static device globals)
__device__ __align__(16) float g_g0[Bn*Cn*HW];     // grad-act(c0)
__device__ __align__(16) float g_a1[Bn*HW];        // act(c1)
__device__ __align__(16) float g_part[NG*Bn*HW];   // channel-group partial sums

__constant__ float c_f0[Cn*25];
__constant__ float c_f1[Cn*25];
__constant__ float c_b0[Cn];
__constant__ float c_b1[1];

__device__ __forceinline__ float ex2f_(float x){ float r; asm("ex2.approx.f32 %0,%1;" : "=f"(r) : "f"(x)); return r; }
__device__ __forceinline__ float rcpf_(float x){ float r; asm("rcp.approx.f32 %0,%1;" : "=f"(r) : "f"(x)); return r; }

#define CJ1 0.60653065971f
#define CJ2 0.13533528324f
#define CJ3 0.01110899654f
#define CJ4 0.00033546262f
#define L2E 1.44269504089f

// 9-tap RBF via exp decomposition: exp(-(s-j)^2/2) = E0 * r^j * c_j
__device__ __forceinline__ void rbf9(float v, const float* __restrict__ w,
                                     float& a_out, float& g_out) {
    float u  = fmaf(v, 0.1f, 31.0f);
    float pf = rintf(u);
    pf = fminf(fmaxf(pf, 4.0f), 58.0f);
    int   pc = (int)pf;
    float s  = u - pf;
    s = fminf(fmaxf(s, -9.0f), 9.0f);
    float r  = ex2f_(s * L2E);
    float E0 = ex2f_(s * s * (-0.5f * L2E));
    float q  = rcpf_(r);
    float r2 = r*r, r3 = r2*r, r4 = r2*r2;
    float q2 = q*q, q3 = q2*q, q4 = q2*q2;
    float m, A, B;
    m = w[pc-4]*(CJ4*q4); A  = m;  B = m * -4.0f;
    m = w[pc-3]*(CJ3*q3); A += m;  B = fmaf(m, -3.0f, B);
    m = w[pc-2]*(CJ2*q2); A += m;  B = fmaf(m, -2.0f, B);
    m = w[pc-1]*(CJ1*q ); A += m;  B = fmaf(m, -1.0f, B);
    m = w[pc  ];          A += m;
    m = w[pc+1]*(CJ1*r ); A += m;  B = fmaf(m,  1.0f, B);
    m = w[pc+2]*(CJ2*r2); A += m;  B = fmaf(m,  2.0f, B);
    m = w[pc+3]*(CJ3*r3); A += m;  B = fmaf(m,  3.0f, B);
    m = w[pc+4]*(CJ4*r4); A += m;  B = fmaf(m,  4.0f, B);
    a_out = E0 * A;
    g_out = (-0.1f * E0) * fmaf(s, A, -B);
}

// kA: fused conv0 + RBF + conv1-partials. Tile = 32 rows x 128 cols, 2 channels.
// grid (4, 4, 32) = 512 CTAs.
__global__ void __launch_bounds__(256) kA_enc(const float* __restrict__ x,
                                              const float* __restrict__ w0) {
    __shared__ float xs[40][132];   // x rows h0-4..h0+35 clamp, cols -2..129 clamp (x255)
    __shared__ float sa0[36][136];  // a0 rows clamp(h0-2+r), cols -2..133 (rep-pad cols)
    __shared__ float sw0[2*63];
    int tid = threadIdx.x;
    int h0 = blockIdx.x * 32;
    int b  = blockIdx.y;
    int g  = blockIdx.z;            // channels 2g, 2g+1

    for (int i = tid; i < 2*63; i += 256) sw0[i] = w0[(g*2)*63 + i];
    const float* xb = x + b*HW;
    for (int i = tid; i < 40*132; i += 256) {
        int r = i / 132, c = i - r*132;
        int gh = min(max(h0 - 4 + r, 0), Hn-1);
        int gw = min(max(c - 2, 0), Wn-1);
        (&xs[0][0])[i] = xb[gh*Wn + gw] * 255.0f;
    }

    float acc[2][8];
    #pragma unroll
    for (int k = 0; k < 2; ++k)
        #pragma unroll
        for (int j = 0; j < 8; ++j) acc[k][j] = 0.f;

    #pragma unroll 1
    for (int cc = 0; cc < 2; ++cc) {
        int c = g*2 + cc;
        float bias = c_b0[c];
        __syncthreads();                 // prev-channel reads done before overwrite
        // a0 stage: 36 rows x 32 strips of 4 = 1152 units
        #pragma unroll 1
        for (int u = tid; u < 1152; u += 256) {
            int ri = u >> 5;
            int s  = u & 31;
            int w  = s * 4;
            int hc = min(max(h0 - 2 + ri, 0), Hn-1);
            int xr = hc - h0 + 2;        // xs row for dy=0 (x row hc-2 clamped)
            float a0v=bias, a1v=bias, a2v=bias, a3v=bias;
            #pragma unroll
            for (int dy = 0; dy < 5; ++dy) {
                float4 va = *(const float4*)&xs[xr+dy][w];
                float4 vb = *(const float4*)&xs[xr+dy][w+4];
                float v[8] = {va.x, va.y, va.z, va.w, vb.x, vb.y, vb.z, vb.w};
                #pragma unroll
                for (int dx = 0; dx < 5; ++dx) {
                    float f = c_f0[c*25 + dy*5 + dx];
                    a0v = fmaf(v[dx+0], f, a0v);
                    a1v = fmaf(v[dx+1], f, a1v);
                    a2v = fmaf(v[dx+2], f, a2v);
                    a3v = fmaf(v[dx+3], f, a3v);
                }
            }
            const float* wr = &sw0[cc*63];
            float aa0,gg0, aa1,gg1, aa2,gg2, aa3,gg3;
            rbf9(a0v, wr, aa0, gg0);
            rbf9(a1v, wr, aa1, gg1);
            rbf9(a2v, wr, aa2, gg2);
            rbf9(a3v, wr, aa3, gg3);
            sa0[ri][2+w+0] = aa0;
            sa0[ri][2+w+1] = aa1;
            sa0[ri][2+w+2] = aa2;
            sa0[ri][2+w+3] = aa3;
            if (s == 0)  { sa0[ri][0]   = aa0; sa0[ri][1]   = aa0; }
            if (s == 31) { sa0[ri][130] = aa3; sa0[ri][131] = aa3; }
            if (ri >= 2 && ri <= 33) {
                *(float4*)&g_g0[(size_t)(b*Cn + c)*HW + (h0 + ri - 2)*Wn + w]
                    = make_float4(gg0, gg1, gg2, gg3);
            }
        }
        __syncthreads();
        // conv1 accumulate: 32 rows x 16 strips of 8 = 512 units, 2/thread exact
        #pragma unroll
        for (int k = 0; k < 2; ++k) {
            int u = tid + k*256;
            int r = u >> 4;
            int w = (u & 15) * 8;
            #pragma unroll
            for (int ky = 0; ky < 5; ++ky) {
                float4 va = *(const float4*)&sa0[r+ky][w];
                float4 vb = *(const float4*)&sa0[r+ky][w+4];
                float4 vc = *(const float4*)&sa0[r+ky][w+8];
                float v[12] = {va.x,va.y,va.z,va.w, vb.x,vb.y,vb.z,vb.w,
                               vc.x,vc.y,vc.z,vc.w};
                #pragma unroll
                for (int kx = 0; kx < 5; ++kx) {
                    float f = c_f1[c*25 + ky*5 + kx];
                    #pragma unroll
                    for (int j = 0; j < 8; ++j)
                        acc[k][j] = fmaf(v[kx+j], f, acc[k][j]);
                }
            }
        }
    }
    #pragma unroll
    for (int k = 0; k < 2; ++k) {
        int u = tid + k*256;
        int r = u >> 4;
        int w = (u & 15) * 8;
        float* pp = &g_part[(size_t)g*(Bn*HW) + b*HW + (h0+r)*Wn + w];
        *(float4*)(pp)     = make_float4(acc[k][0], acc[k][1], acc[k][2], acc[k][3]);
        *(float4*)(pp + 4) = make_float4(acc[k][4], acc[k][5], acc[k][6], acc[k][7]);
    }
}

// K2b: a1 = act(sum(partials) + b1, w1), 4 px/thread
__global__ void k2b_reduce_act(const float* __restrict__ w1) {
    __shared__ float sw[Pn];
    int tid = threadIdx.x;
    if (tid < Pn) sw[tid] = w1[tid];
    __syncthreads();
    int p4 = blockIdx.x * 256 + tid;      // float4 pixel index
    float b1v = c_b1[0];
    float4 s = make_float4(b1v, b1v, b1v, b1v);
    #pragma unroll
    for (int g = 0; g < NG; ++g) {
        float4 v = *(const float4*)&g_part[(size_t)g*(Bn*HW) + p4*4];
        s.x += v.x; s.y += v.y; s.z += v.z; s.w += v.w;
    }
    float a0,g0, a1,g1, a2,g2, a3,g3;
    rbf9(s.x, sw, a0, g0);
    rbf9(s.y, sw, a1, g1);
    rbf9(s.z, sw, a2, g2);
    rbf9(s.w, sw, a3, g3);
    *(float4*)&g_a1[p4*4] = make_float4(a0, a1, a2, a3);
}

// K5: fused deconv1*g0 + deconv0-partials. Tile = 32 rows x 128 cols, 2 channels.
__global__ void __launch_bounds__(256) k5_fused_deconv() {
    __shared__ float sa1[40][136];  // a1 rows h0-4..h0+35, cols -4..131, zero pad
    __shared__ float sd[36][132];   // d rows h0-2..h0+33, cols -2..129 (0 outside img)
    int tid = threadIdx.x;
    int h0 = blockIdx.x * 32;
    int b  = blockIdx.y;
    int g  = blockIdx.z;
    const float* ab = g_a1 + b*HW;

    for (int i = tid; i < 40*136; i += 256) {
        int r = i / 136, c = i - r*136;
        int gh = h0 - 4 + r, gw = c - 4;
        (&sa1[0][0])[i] = ((unsigned)gh < (unsigned)Hn && (unsigned)gw < (unsigned)Wn)
                          ? ab[gh*Wn + gw] : 0.f;
    }

    float acc[2][8];
    #pragma unroll
    for (int k = 0; k < 2; ++k)
        #pragma unroll
        for (int j = 0; j < 8; ++j) acc[k][j] = 0.f;

    #pragma unroll 1
    for (int cc = 0; cc < 2; ++cc) {
        int c = g*2 + cc;
        const float* g0c = g_g0 + (size_t)(b*Cn + c)*HW;
        __syncthreads();
        // d stage: 36 rows x 33 strips of 4 = 1188 units
        #pragma unroll 1
        for (int u = tid; u < 1188; u += 256) {
            int r  = u / 33;
            int s  = u - r*33;
            int c0 = s * 4;                 // sd col base; d col = c0-2+j
            int hd = h0 - 2 + r;
            float d0=0.f, d1=0.f, d2=0.f, d3=0.f;
            #pragma unroll
            for (int ky = 0; ky < 5; ++ky) {
                float4 va = *(const float4*)&sa1[r+ky][c0];
                float4 vb = *(const float4*)&sa1[r+ky][c0+4];
                float v[8] = {va.x, va.y, va.z, va.w, vb.x, vb.y, vb.z, vb.w};
                #pragma unroll
                for (int kx = 0; kx < 5; ++kx) {
                    float f = c_f1[c*25 + 24 - (ky*5 + kx)];
                    d0 = fmaf(v[kx+0], f, d0);
                    d1 = fmaf(v[kx+1], f, d1);
                    d2 = fmaf(v[kx+2], f, d2);
                    d3 = fmaf(v[kx+3], f, d3);
                }
            }
            bool rv = (unsigned)hd < (unsigned)Hn;
            int hs = min(max(hd, 0), Hn-1);
            const float* g0r = g0c + hs*Wn;
            int w0c = c0 - 2;
            int wa = min(max(w0c+0, 0), Wn-1);
            int wb = min(max(w0c+1, 0), Wn-1);
            int wc = min(max(w0c+2, 0), Wn-1);
            int wd = min(max(w0c+3, 0), Wn-1);
            d0 = (rv && (unsigned)(w0c+0) < (unsigned)Wn) ? d0 * g0r[wa] : 0.f;
            d1 = (rv && (unsigned)(w0c+1) < (unsigned)Wn) ? d1 * g0r[wb] : 0.f;
            d2 = (rv && (unsigned)(w0c+2) < (unsigned)Wn) ? d2 * g0r[wc] : 0.f;
            d3 = (rv && (unsigned)(w0c+3) < (unsigned)Wn) ? d3 * g0r[wd] : 0.f;
            *(float4*)&sd[r][c0] = make_float4(d0, d1, d2, d3);
        }
        __syncthreads();
        // deconv0 accumulate: 32 rows x 16 strips of 8 = 512 units, 2/thread
        #pragma unroll
        for (int k = 0; k < 2; ++k) {
            int u = tid + k*256;
            int r = u >> 4;
            int w = (u & 15) * 8;
            #pragma unroll
            for (int ky = 0; ky < 5; ++ky) {
                float4 va = *(const float4*)&sd[r+ky][w];
                float4 vb = *(const float4*)&sd[r+ky][w+4];
                float4 vc = *(const float4*)&sd[r+ky][w+8];
                float v[12] = {va.x,va.y,va.z,va.w, vb.x,vb.y,vb.z,vb.w,
                               vc.x,vc.y,vc.z,vc.w};
                #pragma unroll
                for (int kx = 0; kx < 5; ++kx) {
                    float f = c_f0[c*25 + 24 - (ky*5 + kx)];
                    #pragma unroll
                    for (int j = 0; j < 8; ++j)
                        acc[k][j] = fmaf(v[kx+j], f, acc[k][j]);
                }
            }
        }
    }
    #pragma unroll
    for (int k = 0; k < 2; ++k) {
        int u = tid + k*256;
        int r = u >> 4;
        int w = (u & 15) * 8;
        float* pp = &g_part[(size_t)g*(Bn*HW) + b*HW + (h0+r)*Wn + w];
        *(float4*)(pp)     = make_float4(acc[k][0], acc[k][1], acc[k][2], acc[k][3]);
        *(float4*)(pp + 4) = make_float4(acc[k][4], acc[k][5], acc[k][6], acc[k][7]);
    }
}

// K4b: out = x - sum(partials)/255 - exp(lam)*(x - y), 4 px/thread
__global__ void k4b_reduce_out(const float* __restrict__ x,
                               const float* __restrict__ y,
                               const float* __restrict__ lam_param,
                               float* __restrict__ out) {
    int p4 = blockIdx.x * 256 + threadIdx.x;
    float4 s = make_float4(0.f, 0.f, 0.f, 0.f);
    #pragma unroll
    for (int g = 0; g < NG; ++g) {
        float4 v = *(const float4*)&g_part[(size_t)g*(Bn*HW) + p4*4];
        s.x += v.x; s.y += v.y; s.z += v.z; s.w += v.w;
    }
    float e = __expf(lam_param[0]);
    float4 xv = *(const float4*)&x[p4*4];
    float4 yv = *(const float4*)&y[p4*4];
    float4 o;
    o.x = xv.x - s.x*(1.0f/255.0f) - e*(xv.x - yv.x);
    o.y = xv.y - s.y*(1.0f/255.0f) - e*(xv.y - yv.y);
    o.z = xv.z - s.z*(1.0f/255.0f) - e*(xv.z - yv.z);
    o.w = xv.w - s.w*(1.0f/255.0f) - e*(xv.w - yv.w);
    *(float4*)&out[p4*4] = o;
}

extern "C" void kernel_launch(void* const* d_in, const int* in_sizes, int n_in,
                              void* d_out, int out_size) {
    const float* x   = (const float*)d_in[0];
    const float* y   = (const float*)d_in[1];
    // d_in[2] = lam (ignored)
    const float* f0  = (const float*)d_in[3];
    const float* b0  = (const float*)d_in[4];
    const float* f1  = (const float*)d_in[5];
    const float* b1  = (const float*)d_in[6];
    const float* w0  = (const float*)d_in[7];
    const float* w1  = (const float*)d_in[8];
    const float* lam = (const float*)d_in[9];
    float* out = (float*)d_out;

    cudaMemcpyToSymbolAsync(c_f0, f0, Cn*25*sizeof(float), 0, cudaMemcpyDeviceToDevice, 0);
    cudaMemcpyToSymbolAsync(c_f1, f1, Cn*25*sizeof(float), 0, cudaMemcpyDeviceToDevice, 0);
    cudaMemcpyToSymbolAsync(c_b0, b0, Cn*sizeof(float),    0, cudaMemcpyDeviceToDevice, 0);
    cudaMemcpyToSymbolAsync(c_b1, b1, sizeof(float),       0, cudaMemcpyDeviceToDevice, 0);

    dim3 gT(Hn/32, Bn, NG);        // (4, 4, 32) = 512 CTAs
    dim3 gR(Bn*HW/4/256);          // (64) — 4 px per thread

    kA_enc<<<gT, 256>>>(x, w0);
    k2b_reduce_act<<<gR, 256>>>(w1);
    k5_fused_deconv<<<gT, 256>>>();
    k4b_reduce_out<<<gR, 256>>>(x, y, lam, out);
}